// round 1
// baseline (speedup 1.0000x reference)
#include <cuda_runtime.h>
#include <math.h>

// Problem constants
#define NN 50000
#define EE 800000
#define DD 32
// ev MLP: [E,96] -> relu -> [E,128] -> [E,16]
// fc MLP: [E,22] -> relu -> [E,64]  -> [E,512] (=16x32), contracted with v -> [E,32]
// nu MLP: [N,64] -> relu -> [N,128] -> [N,32]

// ---------------- device scratch (no allocs allowed) ----------------
__device__ float g_v[EE * 16];        // edge value MLP output
__device__ float g_ntmp[NN * DD];     // scatter-add accumulator

extern __shared__ float smem[];

// ---------------- zero node_tmp ----------------
__global__ void zero_ntmp_kernel() {
    int i = blockIdx.x * blockDim.x + threadIdx.x;
    if (i < NN * DD) g_ntmp[i] = 0.0f;
}

// ---------------- E1: edge value MLP -> g_v ----------------
// smem: ev_w1[96*128] | ev_w2[128*16] | xs[256*97] | src[256] dst[256]
#define E1_XS 97
#define E1_SMEM_BYTES ((96*128 + 128*16 + 256*E1_XS) * 4 + 2*256*4)

__global__ void __launch_bounds__(256) edge_val_kernel(
    const float* __restrict__ hn, const float* __restrict__ he,
    const int* __restrict__ esrc, const int* __restrict__ edst,
    const float* __restrict__ ev_w1, const float* __restrict__ ev_w2)
{
    float* w1s = smem;                      // [k*128 + j]
    float* w2s = w1s + 96*128;              // [j*16 + o]
    float* xs  = w2s + 128*16;              // [e*97 + k]
    int*   ss  = (int*)(xs + 256*E1_XS);
    int*   dsi = ss + 256;

    const int tid = threadIdx.x;
    const int e0  = blockIdx.x * 256;       // EE % 256 == 0

    {
        const float4* g1 = (const float4*)ev_w1;
        float4* s1 = (float4*)w1s;
        #pragma unroll 4
        for (int i = tid; i < (96*128)/4; i += 256) s1[i] = g1[i];
        const float4* g2 = (const float4*)ev_w2;
        float4* s2 = (float4*)w2s;
        for (int i = tid; i < (128*16)/4; i += 256) s2[i] = g2[i];
    }
    ss[tid]  = esrc[e0 + tid];
    dsi[tid] = edst[e0 + tid];
    __syncthreads();

    // stage x = [he | hn[src] | hn[dst]], coalesced (one 128B row per warp step)
    for (int i = tid; i < 256*32; i += 256) {
        int e = i >> 5, o = i & 31;
        xs[e*E1_XS +      o] = he[(size_t)(e0+e)*32 + o];
        xs[e*E1_XS + 32 + o] = hn[(size_t)ss[e]*32 + o];
        xs[e*E1_XS + 64 + o] = hn[(size_t)dsi[e]*32 + o];
    }
    __syncthreads();

    const float* x = &xs[tid * E1_XS];
    float v[16];
    #pragma unroll
    for (int o = 0; o < 16; o++) v[o] = 0.0f;

    #pragma unroll 1
    for (int jb = 0; jb < 128; jb += 16) {
        float acc[16];
        #pragma unroll
        for (int j = 0; j < 16; j++) acc[j] = 0.0f;
        #pragma unroll 4
        for (int k = 0; k < 96; k++) {
            float xk = x[k];                      // per-lane, stride-97 conflict-free
            float wv[16];
            const float* wb = &w1s[k*128 + jb];   // broadcast
            #pragma unroll
            for (int q = 0; q < 4; q++) *(float4*)&wv[q*4] = *(const float4*)&wb[q*4];
            #pragma unroll
            for (int j = 0; j < 16; j++) acc[j] = fmaf(xk, wv[j], acc[j]);
        }
        #pragma unroll
        for (int j = 0; j < 16; j++) {
            float h = fmaxf(acc[j], 0.0f);
            float wv[16];
            const float* wb = &w2s[(jb + j)*16];
            #pragma unroll
            for (int q = 0; q < 4; q++) *(float4*)&wv[q*4] = *(const float4*)&wb[q*4];
            #pragma unroll
            for (int o = 0; o < 16; o++) v[o] = fmaf(h, wv[o], v[o]);
        }
    }

    // stage v through smem for coalesced global store
    #pragma unroll
    for (int o = 0; o < 16; o++) xs[tid*E1_XS + o] = v[o];
    __syncthreads();
    for (int i = tid; i < 256*16; i += 256) {
        int e = i >> 4, q = i & 15;
        g_v[(size_t)(e0+e)*16 + q] = xs[e*E1_XS + q];
    }
}

// ---------------- E2: fc MLP + contraction + residual + scatter ----------------
// smem: fc_w2[64*512] | fc_w1[22*64] | ys[256*23] | vs[256*17] | hs[256*33]
#define E2_YS 23
#define E2_VS 17
#define E2_HS 33
#define E2_SMEM_BYTES ((64*512 + 22*64 + 256*E2_YS + 256*E2_VS + 256*E2_HS) * 4)

__global__ void __launch_bounds__(256) edge_msg_kernel(
    const float* __restrict__ pos, const float* __restrict__ fes,
    const float* __restrict__ norm,
    const int* __restrict__ esrc, const int* __restrict__ edst,
    const float* __restrict__ he,
    const float* __restrict__ fc_w1, const float* __restrict__ fc_w2,
    float* __restrict__ out_hen)
{
    float* w2f = smem;                 // [h*512 + v*32 + o]
    float* w1f = w2f + 64*512;         // [k*64 + h]
    float* ys  = w1f + 22*64;          // [e*23 + k]
    float* vs  = ys  + 256*E2_YS;      // [e*17 + v]
    float* hs  = vs  + 256*E2_VS;      // [e*33 + o]

    const int tid = threadIdx.x;
    const int e0  = blockIdx.x * 256;
    const int e   = e0 + tid;

    {
        const float4* g2 = (const float4*)fc_w2;
        float4* s2 = (float4*)w2f;
        #pragma unroll 4
        for (int i = tid; i < (64*512)/4; i += 256) s2[i] = g2[i];
        const float4* g1 = (const float4*)fc_w1;
        float4* s1 = (float4*)w1f;
        for (int i = tid; i < (22*64)/4; i += 256) s1[i] = g1[i];
    }

    const int sidx = esrc[e];
    const int didx = edst[e];
    // pos gathers (pos fits easily in L2)
    ys[tid*E2_YS + 0] = pos[(size_t)sidx*3 + 0];
    ys[tid*E2_YS + 1] = pos[(size_t)sidx*3 + 1];
    ys[tid*E2_YS + 2] = pos[(size_t)sidx*3 + 2];
    ys[tid*E2_YS + 3] = pos[(size_t)didx*3 + 0];
    ys[tid*E2_YS + 4] = pos[(size_t)didx*3 + 1];
    ys[tid*E2_YS + 5] = pos[(size_t)didx*3 + 2];
    for (int i = tid; i < 256*16; i += 256) {
        int ee = i >> 4, q = i & 15;
        ys[ee*E2_YS + 6 + q] = fes[(size_t)(e0+ee)*16 + q];
        vs[ee*E2_VS + q]     = g_v[(size_t)(e0+ee)*16 + q];
    }
    for (int i = tid; i < 256*32; i += 256) {
        int ee = i >> 5, o = i & 31;
        hs[ee*E2_HS + o] = he[(size_t)(e0+ee)*32 + o];
    }
    __syncthreads();

    const float* y    = &ys[tid*E2_YS];
    const float* vrow = &vs[tid*E2_VS];

    float tp[32];
    #pragma unroll
    for (int o = 0; o < 32; o++) tp[o] = 0.0f;

    #pragma unroll 1
    for (int hb = 0; hb < 64; hb += 8) {
        float g[8];
        #pragma unroll
        for (int h = 0; h < 8; h++) g[h] = 0.0f;
        #pragma unroll
        for (int k = 0; k < 22; k++) {
            float yk = y[k];
            float wv[8];
            *(float4*)&wv[0] = *(const float4*)&w1f[k*64 + hb];
            *(float4*)&wv[4] = *(const float4*)&w1f[k*64 + hb + 4];
            #pragma unroll
            for (int h = 0; h < 8; h++) g[h] = fmaf(yk, wv[h], g[h]);
        }
        #pragma unroll
        for (int h8 = 0; h8 < 8; h8++) {
            float gh = fmaxf(g[h8], 0.0f);
            const float* wrow = &w2f[(hb + h8) << 9];
            #pragma unroll 1
            for (int vv = 0; vv < 16; vv++) {
                float coef = gh * vrow[vv];
                float wv[32];
                #pragma unroll
                for (int q = 0; q < 8; q++)
                    *(float4*)&wv[q*4] = *(const float4*)&wrow[vv*32 + q*4];
                #pragma unroll
                for (int o = 0; o < 32; o++) tp[o] = fmaf(coef, wv[o], tp[o]);
            }
        }
    }

    const float nrm = norm[e];
    float* hrow = &hs[tid*E2_HS];
    #pragma unroll
    for (int o = 0; o < 32; o++) {
        float henv = hrow[o] + tp[o];   // residual
        hrow[o] = henv;                 // stage for coalesced store
        atomicAdd(&g_ntmp[(size_t)didx*32 + o], henv * nrm);
    }
    __syncthreads();
    for (int i = tid; i < 256*32; i += 256) {
        int ee = i >> 5, o = i & 31;
        out_hen[(size_t)(e0+ee)*32 + o] = hs[ee*E2_HS + o];
    }
}

// ---------------- K3: node update MLP ----------------
// smem: nu_w1[64*128] | nu_w2[128*32] | xs[256*65]
#define K3_XS 65
#define K3_SMEM_BYTES ((64*128 + 128*32 + 256*K3_XS) * 4)

__global__ void __launch_bounds__(256) node_kernel(
    const float* __restrict__ hn,
    const float* __restrict__ nu_w1, const float* __restrict__ nu_w2,
    float* __restrict__ out_hnn)
{
    float* w1n = smem;                 // [k*128 + j]
    float* w2n = w1n + 64*128;         // [j*32 + o]
    float* xs  = w2n + 128*32;         // [r*65 + k]

    const int tid = threadIdx.x;
    const int n0  = blockIdx.x * 256;

    {
        const float4* g1 = (const float4*)nu_w1;
        float4* s1 = (float4*)w1n;
        #pragma unroll 4
        for (int i = tid; i < (64*128)/4; i += 256) s1[i] = g1[i];
        const float4* g2 = (const float4*)nu_w2;
        float4* s2 = (float4*)w2n;
        for (int i = tid; i < (128*32)/4; i += 256) s2[i] = g2[i];
    }
    for (int i = tid; i < 256*32; i += 256) {
        int r = i >> 5, o = i & 31;
        int n = n0 + r;
        float a = 0.0f, b = 0.0f;
        if (n < NN) { a = hn[(size_t)n*32 + o]; b = g_ntmp[(size_t)n*32 + o]; }
        xs[r*K3_XS + o]      = a;
        xs[r*K3_XS + 32 + o] = b;
    }
    __syncthreads();

    const float* x = &xs[tid * K3_XS];
    float hnu[32];
    #pragma unroll
    for (int o = 0; o < 32; o++) hnu[o] = 0.0f;

    #pragma unroll 1
    for (int jb = 0; jb < 128; jb += 16) {
        float acc[16];
        #pragma unroll
        for (int j = 0; j < 16; j++) acc[j] = 0.0f;
        #pragma unroll 4
        for (int k = 0; k < 64; k++) {
            float xk = x[k];
            float wv[16];
            const float* wb = &w1n[k*128 + jb];
            #pragma unroll
            for (int q = 0; q < 4; q++) *(float4*)&wv[q*4] = *(const float4*)&wb[q*4];
            #pragma unroll
            for (int j = 0; j < 16; j++) acc[j] = fmaf(xk, wv[j], acc[j]);
        }
        #pragma unroll
        for (int j = 0; j < 16; j++) {
            float h = fmaxf(acc[j], 0.0f);
            float wv[32];
            const float* wb = &w2n[(jb + j)*32];
            #pragma unroll
            for (int q = 0; q < 8; q++) *(float4*)&wv[q*4] = *(const float4*)&wb[q*4];
            #pragma unroll
            for (int o = 0; o < 32; o++) hnu[o] = fmaf(h, wv[o], hnu[o]);
        }
    }
    // residual, stage for coalesced store
    #pragma unroll
    for (int o = 0; o < 32; o++) xs[tid*K3_XS + o] = x[o] + hnu[o];
    __syncthreads();
    for (int i = tid; i < 256*32; i += 256) {
        int r = i >> 5, o = i & 31;
        int n = n0 + r;
        if (n < NN) out_hnn[(size_t)n*32 + o] = xs[r*K3_XS + o];
    }
}

// ---------------- launch ----------------
extern "C" void kernel_launch(void* const* d_in, const int* in_sizes, int n_in,
                              void* d_out, int out_size)
{
    const float* hn    = (const float*)d_in[0];
    const float* he    = (const float*)d_in[1];
    const float* pos   = (const float*)d_in[2];
    const float* fes   = (const float*)d_in[3];
    const float* norm  = (const float*)d_in[4];
    const int*   esrc  = (const int*)  d_in[5];
    const int*   edst  = (const int*)  d_in[6];
    const float* ev_w1 = (const float*)d_in[7];
    const float* ev_w2 = (const float*)d_in[8];
    const float* fc_w1 = (const float*)d_in[9];
    const float* fc_w2 = (const float*)d_in[10];
    const float* nu_w1 = (const float*)d_in[11];
    const float* nu_w2 = (const float*)d_in[12];

    float* out_hnn = (float*)d_out;                       // [N,32] first (tuple order)
    float* out_hen = (float*)d_out + (size_t)NN * DD;     // [E,32] second

    cudaFuncSetAttribute(edge_val_kernel, cudaFuncAttributeMaxDynamicSharedMemorySize, E1_SMEM_BYTES);
    cudaFuncSetAttribute(edge_msg_kernel, cudaFuncAttributeMaxDynamicSharedMemorySize, E2_SMEM_BYTES);
    cudaFuncSetAttribute(node_kernel,     cudaFuncAttributeMaxDynamicSharedMemorySize, K3_SMEM_BYTES);

    zero_ntmp_kernel<<<(NN*DD + 255)/256, 256>>>();
    edge_val_kernel<<<EE/256, 256, E1_SMEM_BYTES>>>(hn, he, esrc, edst, ev_w1, ev_w2);
    edge_msg_kernel<<<EE/256, 256, E2_SMEM_BYTES>>>(pos, fes, norm, esrc, edst, he,
                                                    fc_w1, fc_w2, out_hen);
    node_kernel<<<(NN + 255)/256, 256, K3_SMEM_BYTES>>>(hn, nu_w1, nu_w2, out_hnn);
}

// round 3
// speedup vs baseline: 2.4729x; 2.4729x over previous
#include <cuda_runtime.h>
#include <math.h>
#include <stdint.h>

#define NN 50000
#define EE 800000

// ---------------- device scratch (no allocs allowed) ----------------
__device__ float g_v[EE * 16];        // edge value MLP output
__device__ float g_ntmp[NN * 32];     // scatter-add accumulator

extern __shared__ uint32_t smu[];

// ---------------- mma / layout helpers ----------------
__device__ __forceinline__ uint32_t f2tf(float f) {
    uint32_t r; asm("cvt.rna.tf32.f32 %0, %1;" : "=r"(r) : "f"(f)); return r;
}
__device__ __forceinline__ void mma_tf32(float* c, const uint32_t* a, const uint32_t* b) {
    asm("mma.sync.aligned.m16n8k8.row.col.f32.tf32.tf32.f32 "
        "{%0,%1,%2,%3},{%4,%5,%6,%7},{%8,%9},{%0,%1,%2,%3};"
        : "+f"(c[0]), "+f"(c[1]), "+f"(c[2]), "+f"(c[3])
        : "r"(a[0]), "r"(a[1]), "r"(a[2]), "r"(a[3]), "r"(b[0]), "r"(b[1]));
}
// A-fragment permuted store: X[row][col] -> frag layout (LDS.128 per frag)
__device__ __forceinline__ void storeA(uint32_t* A, int KC, int row, int col, uint32_t v) {
    int mc = row >> 4, r = row & 15, gid = r & 7, hi = r >> 3;
    int kc = col >> 3, cc = col & 7, tig = cc & 3, ch = cc >> 2;
    A[((mc * KC + kc) * 32 + gid * 4 + tig) * 4 + hi + 2 * ch] = v;
}
// B-fragment permuted store: W[k][n] -> frag layout (LDS.64 per frag)
__device__ __forceinline__ void storeB(uint32_t* B, int NC, int k, int n, uint32_t v) {
    int kc = k >> 3, kr = k & 7, tig = kr & 3, kh = kr >> 2;
    int nc = n >> 3, gid = n & 7;
    B[((kc * NC + nc) * 32 + gid * 4 + tig) * 2 + kh] = v;
}
__device__ __forceinline__ void ldA(uint32_t* d, const uint32_t* A, int KC, int mc, int kc, int lane) {
    uint4 t = *(const uint4*)&A[((mc * KC + kc) * 32 + lane) * 4];
    d[0] = t.x; d[1] = t.y; d[2] = t.z; d[3] = t.w;
}
__device__ __forceinline__ void ldB(uint32_t* d, const uint32_t* B, int NC, int kc, int nc, int lane) {
    uint2 t = *(const uint2*)&B[((kc * NC + nc) * 32 + lane) * 2];
    d[0] = t.x; d[1] = t.y;
}

// ---------------- zero node_tmp ----------------
__global__ void zero_ntmp_kernel() {
    int i = blockIdx.x * blockDim.x + threadIdx.x;
    if (i < NN * 32) g_ntmp[i] = 0.0f;
}

// =====================================================================
// E1: edge value MLP  X[128,96] -> relu(X@W1[96,128]) @ W2[128,16] -> g_v
// smem u32: B1 12288 | B2 2048 | AX 12288 (8mc x 12kc) | HH 16384 (8mc x 16kc)
// =====================================================================
#define E1_SMEM_BYTES ((12288 + 2048 + 12288 + 16384) * 4)

__global__ void __launch_bounds__(256, 1) edge_val_mma(
    const float* __restrict__ hn, const float* __restrict__ he,
    const int* __restrict__ esrc, const int* __restrict__ edst,
    const float* __restrict__ ev_w1, const float* __restrict__ ev_w2)
{
    uint32_t* B1 = smu;
    uint32_t* B2 = B1 + 12288;
    uint32_t* AX = B2 + 2048;
    uint32_t* HH = AX + 12288;

    const int tid = threadIdx.x, wid = tid >> 5, lane = tid & 31;
    const int gid = lane >> 2, tig = lane & 3;
    const int e0 = blockIdx.x * 128;

    // weights -> B-frag layout (tf32-rounded)
    for (int i = tid; i < 96 * 128; i += 256) storeB(B1, 16, i >> 7, i & 127, f2tf(ev_w1[i]));
    for (int i = tid; i < 128 * 16; i += 256) storeB(B2, 2, i >> 4, i & 15, f2tf(ev_w2[i]));

    // stage X = [he | hn[src] | hn[dst]] -> A-frag layout
    {
        int g = lane >> 3, l8 = lane & 7;
        #pragma unroll 1
        for (int rr = 0; rr < 4; rr++) {
            int row = wid * 16 + rr * 4 + g;
            int e = e0 + row;
            int s = esrc[e], d = edst[e];
            float4 a = *(const float4*)&he[(size_t)e * 32 + l8 * 4];
            float4 b = *(const float4*)&hn[(size_t)s * 32 + l8 * 4];
            float4 c = *(const float4*)&hn[(size_t)d * 32 + l8 * 4];
            int c0 = l8 * 4;
            storeA(AX, 12, row, c0 + 0, f2tf(a.x));
            storeA(AX, 12, row, c0 + 1, f2tf(a.y));
            storeA(AX, 12, row, c0 + 2, f2tf(a.z));
            storeA(AX, 12, row, c0 + 3, f2tf(a.w));
            storeA(AX, 12, row, 32 + c0 + 0, f2tf(b.x));
            storeA(AX, 12, row, 32 + c0 + 1, f2tf(b.y));
            storeA(AX, 12, row, 32 + c0 + 2, f2tf(b.z));
            storeA(AX, 12, row, 32 + c0 + 3, f2tf(b.w));
            storeA(AX, 12, row, 64 + c0 + 0, f2tf(c.x));
            storeA(AX, 12, row, 64 + c0 + 1, f2tf(c.y));
            storeA(AX, 12, row, 64 + c0 + 2, f2tf(c.z));
            storeA(AX, 12, row, 64 + c0 + 3, f2tf(c.w));
        }
    }
    __syncthreads();

    // GEMM1: warps = 2 (m) x 4 (n); relu -> HH in A-frag layout
    {
        int mh = wid >> 2, nq = wid & 3;
        #pragma unroll 1
        for (int mi = 0; mi < 4; mi++) {
            int mc = mh * 4 + mi;
            float acc[4][4] = {};
            #pragma unroll 1
            for (int kc = 0; kc < 12; kc++) {
                uint32_t A[4]; ldA(A, AX, 12, mc, kc, lane);
                #pragma unroll
                for (int j = 0; j < 4; j++) {
                    uint32_t B[2]; ldB(B, B1, 16, kc, nq * 4 + j, lane);
                    mma_tf32(acc[j], A, B);
                }
            }
            #pragma unroll
            for (int j = 0; j < 4; j++) {
                int col = (nq * 4 + j) * 8 + tig * 2;
                storeA(HH, 16, mc * 16 + gid,     col,     f2tf(fmaxf(acc[j][0], 0.f)));
                storeA(HH, 16, mc * 16 + gid,     col + 1, f2tf(fmaxf(acc[j][1], 0.f)));
                storeA(HH, 16, mc * 16 + gid + 8, col,     f2tf(fmaxf(acc[j][2], 0.f)));
                storeA(HH, 16, mc * 16 + gid + 8, col + 1, f2tf(fmaxf(acc[j][3], 0.f)));
            }
        }
    }
    __syncthreads();

    // GEMM2: H[128,128]@W2[128,16]; warp w owns m-chunk w
    {
        int mc = wid;
        float acc[2][4] = {};
        #pragma unroll 1
        for (int kc = 0; kc < 16; kc++) {
            uint32_t A[4]; ldA(A, HH, 16, mc, kc, lane);
            #pragma unroll
            for (int nc = 0; nc < 2; nc++) {
                uint32_t B[2]; ldB(B, B2, 2, kc, nc, lane);
                mma_tf32(acc[nc], A, B);
            }
        }
        #pragma unroll
        for (int nc = 0; nc < 2; nc++) {
            int r0 = e0 + mc * 16 + gid;
            *(float2*)&g_v[(size_t)r0 * 16 + nc * 8 + tig * 2] =
                make_float2(acc[nc][0], acc[nc][1]);
            *(float2*)&g_v[(size_t)(r0 + 8) * 16 + nc * 8 + tig * 2] =
                make_float2(acc[nc][2], acc[nc][3]);
        }
    }
}

// =====================================================================
// E2: fc MLP + contraction + residual + scatter   (tile = 256 edges)
// smem u32: B4 32768 | B3 1536 | AY 6144 (ovl: vS 4352) | GP 16384 (ovl: hS 8448)
//           | DS 256 | NR 256 | ES 256   total 57600 u32 = 230400 B
// =====================================================================
#define E2_SMEM_BYTES (57600 * 4)

__global__ void __launch_bounds__(256, 1) edge_msg_mma(
    const float* __restrict__ pos, const float* __restrict__ fes,
    const float* __restrict__ norm,
    const int* __restrict__ esrc, const int* __restrict__ edst,
    const float* __restrict__ he,
    const float* __restrict__ fc_w1, const float* __restrict__ fc_w2,
    float* __restrict__ out_hen)
{
    uint32_t* B4 = smu;
    uint32_t* B3 = smu + 32768;
    uint32_t* AY = smu + 34304;
    uint32_t* GP = smu + 40448;
    int*      DS = (int*)(smu + 56832);
    float*    NR = (float*)(smu + 57088);
    int*      ES = (int*)(smu + 57344);
    float*    vS = (float*)AY;   // overlay after GEMM3 A no longer needed
    float*    hS = (float*)GP;   // overlay after A-frag preload

    const int tid = threadIdx.x, wid = tid >> 5, lane = tid & 31;
    const int gid = lane >> 2, tig = lane & 3;
    const int e0 = blockIdx.x * 256;

    if (tid < 256) { DS[tid] = edst[e0 + tid]; NR[tid] = norm[e0 + tid]; ES[tid] = esrc[e0 + tid]; }
    __syncthreads();

    // weights
    for (int i = tid; i < 64 * 512; i += 256) storeB(B4, 64, i >> 9, i & 511, f2tf(fc_w2[i]));
    for (int i = tid; i < 24 * 64; i += 256) {
        int k = i >> 6, n = i & 63;
        float w = (k < 22) ? fc_w1[k * 64 + n] : 0.f;
        storeB(B3, 8, k, n, f2tf(w));
    }
    // Y = [pos_src | pos_dst | fes | 0pad] -> A-frag layout (K padded to 24)
    #pragma unroll 1
    for (int i = tid; i < 256 * 24; i += 256) {
        int e = i / 24, c = i - e * 24;
        float v;
        if (c < 6) {
            int node = (c < 3) ? ES[e] : DS[e];
            v = pos[(size_t)node * 3 + ((c < 3) ? c : c - 3)];
        } else if (c < 22) {
            v = fes[(size_t)(e0 + e) * 16 + (c - 6)];
        } else v = 0.f;
        storeA(AY, 3, e, c, f2tf(v));
    }
    __syncthreads();

    // GEMM3: [256,24]@[24,64] -> relu -> GP (A-frag layout); warp w owns mc {2w,2w+1}
    uint32_t Afr[2][8][4];
    #pragma unroll 1
    for (int m = 0; m < 2; m++) {
        int mc = wid * 2 + m;
        float acc[8][4] = {};
        #pragma unroll 1
        for (int kc = 0; kc < 3; kc++) {
            uint32_t A[4]; ldA(A, AY, 3, mc, kc, lane);
            #pragma unroll
            for (int nc = 0; nc < 8; nc++) {
                uint32_t B[2]; ldB(B, B3, 8, kc, nc, lane);
                mma_tf32(acc[nc], A, B);
            }
        }
        #pragma unroll
        for (int nc = 0; nc < 8; nc++) {
            int col = nc * 8 + tig * 2;
            storeA(GP, 8, mc * 16 + gid,     col,     f2tf(fmaxf(acc[nc][0], 0.f)));
            storeA(GP, 8, mc * 16 + gid,     col + 1, f2tf(fmaxf(acc[nc][1], 0.f)));
            storeA(GP, 8, mc * 16 + gid + 8, col,     f2tf(fmaxf(acc[nc][2], 0.f)));
            storeA(GP, 8, mc * 16 + gid + 8, col + 1, f2tf(fmaxf(acc[nc][3], 0.f)));
        }
    }
    __syncwarp();
    // preload this warp's 32-edge A tile (K=64) into registers; reused for all 16 v-cols
    #pragma unroll
    for (int m = 0; m < 2; m++)
        #pragma unroll
        for (int kc = 0; kc < 8; kc++) ldA(Afr[m][kc], GP, 8, wid * 2 + m, kc, lane);
    __syncthreads();

    // overlay staging: v tile and he tile (coalesced)
    for (int i = tid; i < 256 * 16; i += 256) {
        int e = i >> 4, q = i & 15;
        vS[e * 17 + q] = g_v[(size_t)(e0 + e) * 16 + q];
    }
    for (int i = tid; i < 256 * 32; i += 256) {
        int e = i >> 5, o = i & 31;
        hS[e * 33 + o] = he[(size_t)(e0 + e) * 32 + o];
    }
    __syncthreads();

    // GEMM4 [32,64]@[64,512] fused with contraction tp[e,o] += v[e,vv]*T[e,vv*32+o]
    float tp[2][4][4] = {};
    #pragma unroll 1
    for (int vv = 0; vv < 16; vv++) {
        float acc[2][4][4] = {};
        #pragma unroll
        for (int kc = 0; kc < 8; kc++) {
            #pragma unroll
            for (int j = 0; j < 4; j++) {
                uint32_t B[2]; ldB(B, B4, 64, kc, vv * 4 + j, lane);
                mma_tf32(acc[0][j], Afr[0][kc], B);
                mma_tf32(acc[1][j], Afr[1][kc], B);
            }
        }
        #pragma unroll
        for (int m = 0; m < 2; m++) {
            int rb = wid * 32 + m * 16;
            float va = vS[(rb + gid) * 17 + vv];
            float vb = vS[(rb + gid + 8) * 17 + vv];
            #pragma unroll
            for (int j = 0; j < 4; j++) {
                tp[m][j][0] = fmaf(va, acc[m][j][0], tp[m][j][0]);
                tp[m][j][1] = fmaf(va, acc[m][j][1], tp[m][j][1]);
                tp[m][j][2] = fmaf(vb, acc[m][j][2], tp[m][j][2]);
                tp[m][j][3] = fmaf(vb, acc[m][j][3], tp[m][j][3]);
            }
        }
    }
    // residual add into staged he (disjoint addresses per lane/warp)
    #pragma unroll
    for (int m = 0; m < 2; m++) {
        int rb = wid * 32 + m * 16;
        #pragma unroll
        for (int j = 0; j < 4; j++) {
            int o = j * 8 + tig * 2;
            hS[(rb + gid) * 33 + o]         += tp[m][j][0];
            hS[(rb + gid) * 33 + o + 1]     += tp[m][j][1];
            hS[(rb + gid + 8) * 33 + o]     += tp[m][j][2];
            hS[(rb + gid + 8) * 33 + o + 1] += tp[m][j][3];
        }
    }
    __syncthreads();
    // coalesced hen store + scatter atomics
    for (int i = tid; i < 256 * 32; i += 256) {
        int e = i >> 5, o = i & 31;
        float hv = hS[e * 33 + o];
        out_hen[(size_t)(e0 + e) * 32 + o] = hv;
        atomicAdd(&g_ntmp[(size_t)DS[e] * 32 + o], hv * NR[e]);
    }
}

// =====================================================================
// K3: node update MLP (scalar fp32 — 79us measured, fine for now)
// =====================================================================
#define K3_XS 65
#define K3_SMEM_BYTES ((64*128 + 128*32 + 256*K3_XS) * 4)

__global__ void __launch_bounds__(256) node_kernel(
    const float* __restrict__ hn,
    const float* __restrict__ nu_w1, const float* __restrict__ nu_w2,
    float* __restrict__ out_hnn)
{
    float* smf = (float*)smu;
    float* w1n = smf;
    float* w2n = w1n + 64 * 128;
    float* xs  = w2n + 128 * 32;

    const int tid = threadIdx.x;
    const int n0  = blockIdx.x * 256;

    {
        const float4* g1 = (const float4*)nu_w1;
        float4* s1 = (float4*)w1n;
        #pragma unroll 4
        for (int i = tid; i < (64 * 128) / 4; i += 256) s1[i] = g1[i];
        const float4* g2 = (const float4*)nu_w2;
        float4* s2 = (float4*)w2n;
        for (int i = tid; i < (128 * 32) / 4; i += 256) s2[i] = g2[i];
    }
    for (int i = tid; i < 256 * 32; i += 256) {
        int r = i >> 5, o = i & 31;
        int n = n0 + r;
        float a = 0.0f, b = 0.0f;
        if (n < NN) { a = hn[(size_t)n * 32 + o]; b = g_ntmp[(size_t)n * 32 + o]; }
        xs[r * K3_XS + o]      = a;
        xs[r * K3_XS + 32 + o] = b;
    }
    __syncthreads();

    const float* x = &xs[tid * K3_XS];
    float hnu[32];
    #pragma unroll
    for (int o = 0; o < 32; o++) hnu[o] = 0.0f;

    #pragma unroll 1
    for (int jb = 0; jb < 128; jb += 16) {
        float acc[16];
        #pragma unroll
        for (int j = 0; j < 16; j++) acc[j] = 0.0f;
        #pragma unroll 4
        for (int k = 0; k < 64; k++) {
            float xk = x[k];
            float wv[16];
            const float* wb = &w1n[k * 128 + jb];
            #pragma unroll
            for (int q = 0; q < 4; q++) *(float4*)&wv[q * 4] = *(const float4*)&wb[q * 4];
            #pragma unroll
            for (int j = 0; j < 16; j++) acc[j] = fmaf(xk, wv[j], acc[j]);
        }
        #pragma unroll
        for (int j = 0; j < 16; j++) {
            float h = fmaxf(acc[j], 0.0f);
            float wv[32];
            const float* wb = &w2n[(jb + j) * 32];
            #pragma unroll
            for (int q = 0; q < 8; q++) *(float4*)&wv[q * 4] = *(const float4*)&wb[q * 4];
            #pragma unroll
            for (int o = 0; o < 32; o++) hnu[o] = fmaf(h, wv[o], hnu[o]);
        }
    }
    #pragma unroll
    for (int o = 0; o < 32; o++) xs[tid * K3_XS + o] = x[o] + hnu[o];
    __syncthreads();
    for (int i = tid; i < 256 * 32; i += 256) {
        int r = i >> 5, o = i & 31;
        int n = n0 + r;
        if (n < NN) out_hnn[(size_t)n * 32 + o] = xs[r * K3_XS + o];
    }
}

// ---------------- launch ----------------
extern "C" void kernel_launch(void* const* d_in, const int* in_sizes, int n_in,
                              void* d_out, int out_size)
{
    const float* hn    = (const float*)d_in[0];
    const float* he    = (const float*)d_in[1];
    const float* pos   = (const float*)d_in[2];
    const float* fes   = (const float*)d_in[3];
    const float* norm  = (const float*)d_in[4];
    const int*   esrc  = (const int*)  d_in[5];
    const int*   edst  = (const int*)  d_in[6];
    const float* ev_w1 = (const float*)d_in[7];
    const float* ev_w2 = (const float*)d_in[8];
    const float* fc_w1 = (const float*)d_in[9];
    const float* fc_w2 = (const float*)d_in[10];
    const float* nu_w1 = (const float*)d_in[11];
    const float* nu_w2 = (const float*)d_in[12];

    float* out_hnn = (float*)d_out;                       // [N,32] first (tuple order)
    float* out_hen = (float*)d_out + (size_t)NN * 32;     // [E,32] second

    cudaFuncSetAttribute(edge_val_mma, cudaFuncAttributeMaxDynamicSharedMemorySize, E1_SMEM_BYTES);
    cudaFuncSetAttribute(edge_msg_mma, cudaFuncAttributeMaxDynamicSharedMemorySize, E2_SMEM_BYTES);
    cudaFuncSetAttribute(node_kernel,  cudaFuncAttributeMaxDynamicSharedMemorySize, K3_SMEM_BYTES);

    zero_ntmp_kernel<<<(NN * 32 + 255) / 256, 256>>>();
    edge_val_mma<<<EE / 128, 256, E1_SMEM_BYTES>>>(hn, he, esrc, edst, ev_w1, ev_w2);
    edge_msg_mma<<<EE / 256, 256, E2_SMEM_BYTES>>>(pos, fes, norm, esrc, edst, he,
                                                   fc_w1, fc_w2, out_hen);
    node_kernel<<<(NN + 255) / 256, 256, K3_SMEM_BYTES>>>(hn, nu_w1, nu_w2, out_hnn);
}